// round 1
// baseline (speedup 1.0000x reference)
#include <cuda_runtime.h>
#include <math.h>

#define Bn 2048
#define Nn 256
#define Cc 96
#define Hh 3
#define Dd 32
#define N4 64
#define CI 288   // 3*C

// ---------------- scratch (device globals; no allocations allowed) ----------
__device__ float g_qn[(size_t)Bn*Nn*Cc];            // normalized q, (B,N,C)
__device__ float g_A [(size_t)Bn*N4*Cc];            // low-band tokens (B,64,C)
__device__ float g_hcat[(size_t)Bn*N4*CI];          // high subbands token-major (B,64,3C)
__device__ float g_xh[(size_t)Bn*N4*Cc];            // conv output token-major (B,64,C)
__device__ float g_k[2][(size_t)Bn*Hh*N4*Dd];       // normalized+scaled keys (B,H,64,32)
__device__ float g_v[2][(size_t)Bn*Hh*N4*Dd];       // values (B,H,64,32)
__device__ float g_attn[2][(size_t)Bn*Hh*Nn*Dd];    // attention out (B,H,N,32)
__device__ float g_Wc[Cc*192];                      // folded fuse+proj weight (96,192)
__device__ float g_bc[Cc];                          // folded bias

// ---------------- fold proj @ fuse into one GEMM weight ---------------------
__global__ void k_combine(const float* __restrict__ fw, const float* __restrict__ fb,
                          const float* __restrict__ pw, const float* __restrict__ pb) {
    int gid = blockIdx.x * 256 + threadIdx.x;   // 96*192 = 18432 = 72 blocks
    if (gid < 96 * 192) {
        int c2 = gid / 192, e = gid % 192;
        float s = 0.f;
        #pragma unroll 4
        for (int c1 = 0; c1 < 96; c1++) s += pw[c2 * 96 + c1] * fw[c1 * 192 + e];
        g_Wc[gid] = s;
    }
    if (gid < 96) {
        float s = pb[gid];
        #pragma unroll 4
        for (int c1 = 0; c1 < 96; c1++) s += pw[gid * 96 + c1] * fb[c1];
        g_bc[gid] = s;
    }
}

// ---------------- q = x @ q_w^T + b, per-head l2norm -------------------------
__global__ __launch_bounds__(256) void k_q(const float* __restrict__ x,
                                           const float* __restrict__ w,
                                           const float* __restrict__ bias) {
    extern __shared__ float sm[];
    float* Ws = sm;            // [96 k][96 o]
    float* Xs = sm + 96 * 96;  // [64 r][96 k]
    int tid = threadIdx.x;
    int row0 = blockIdx.x * 64;
    for (int idx = tid; idx < 96 * 96; idx += 256) {
        int k = idx % 96, o = idx / 96;
        Ws[k * 96 + o] = w[idx];
    }
    for (int idx = tid; idx < 64 * 96; idx += 256)
        Xs[idx] = x[(size_t)row0 * 96 + idx];
    __syncthreads();
    int lane = tid & 31, rg = tid >> 5;
    float acc[8][3];
    #pragma unroll
    for (int r = 0; r < 8; r++) { acc[r][0] = 0.f; acc[r][1] = 0.f; acc[r][2] = 0.f; }
    const float* Xr = Xs + rg * 8 * 96;
    #pragma unroll 1
    for (int k4 = 0; k4 < 96; k4 += 4) {
        float4 xv[8];
        #pragma unroll
        for (int r = 0; r < 8; r++) xv[r] = *(const float4*)(Xr + r * 96 + k4);
        #pragma unroll
        for (int kk = 0; kk < 4; kk++) {
            float w0 = Ws[(k4 + kk) * 96 + lane];
            float w1 = Ws[(k4 + kk) * 96 + lane + 32];
            float w2 = Ws[(k4 + kk) * 96 + lane + 64];
            #pragma unroll
            for (int r = 0; r < 8; r++) {
                float xs = (&xv[r].x)[kk];
                acc[r][0] += xs * w0; acc[r][1] += xs * w1; acc[r][2] += xs * w2;
            }
        }
    }
    #pragma unroll
    for (int j = 0; j < 3; j++) {
        float bj = bias[lane + 32 * j];
        #pragma unroll
        for (int r = 0; r < 8; r++) {
            float v = acc[r][j] + bj;
            float ss = v * v;
            #pragma unroll
            for (int off = 16; off; off >>= 1) ss += __shfl_xor_sync(0xffffffffu, ss, off);
            float inv = 1.0f / fmaxf(sqrtf(ss), 1e-12f);
            g_qn[(size_t)(row0 + rg * 8 + r) * 96 + lane + 32 * j] = v * inv;
        }
    }
}

// ---------------- NLWT: x (B,N,C as B,C,16,16) -> A + high concat ------------
__global__ __launch_bounds__(256) void k_nlwt(const float* __restrict__ x) {
    int gid = blockIdx.x * 256 + threadIdx.x;   // Bn*64*96 threads exactly
    int c = gid % 96;
    int pos = (gid / 96) & 63;
    int b = gid / (96 * 64);
    int i = pos >> 3, j = pos & 7;
    int i2 = (i + 1) & 7, j2 = (j + 1) & 7;
    const float* xb = x + (size_t)b * 256 * 96;
    #define LDX(yy, xx) xb[((yy) * 16 + (xx)) * 96 + c]
    // t0 from block (i,j): row 0 of U1
    float a0 = LDX(2*i, 2*j),  a1 = LDX(2*i, 2*j+1),  a2 = LDX(2*i+1, 2*j),  a3 = LDX(2*i+1, 2*j+1);
    float t0 =  0.8664f*a0 + 0.1026f*a1 + 0.4852f*a2 - 0.0574f*a3;
    // t1 from block (i+1,j): row 1 of U1 (roll -1 along h)
    float b0 = LDX(2*i2, 2*j), b1 = LDX(2*i2, 2*j+1), b2 = LDX(2*i2+1, 2*j), b3 = LDX(2*i2+1, 2*j+1);
    float t1 = -0.1026f*b0 + 0.8664f*b1 - 0.0574f*b2 - 0.4852f*b3;
    // t2 from block (i,j+1): row 2 of U1 (roll -1 along w)
    float c0 = LDX(2*i, 2*j2), c1 = LDX(2*i, 2*j2+1), c2 = LDX(2*i+1, 2*j2), c3 = LDX(2*i+1, 2*j2+1);
    float t2 =  0.4852f*c0 + 0.0574f*c1 - 0.8664f*c2 + 0.1026f*c3;
    // t3 from block (i+1,j+1): row 3 of U1
    float d0 = LDX(2*i2, 2*j2), d1 = LDX(2*i2, 2*j2+1), d2 = LDX(2*i2+1, 2*j2), d3 = LDX(2*i2+1, 2*j2+1);
    float t3 =  0.0574f*d0 - 0.4852f*d1 - 0.1026f*d2 - 0.8664f*d3;
    #undef LDX
    float Av =  1.3968f*t0 + 0.2212f*t1 - 0.2212f*t2 - 1.3968f*t3;
    float Bv = -0.2212f*t0 + 1.3968f*t1 - 1.3968f*t2 + 0.2212f*t3;
    float Cv = -0.5412f*t0 - 1.3066f*t1 - 1.3066f*t2 - 0.5412f*t3;
    float Dv =  1.3066f*t0 - 0.5412f*t1 - 0.5412f*t2 + 1.3066f*t3;
    g_A[(size_t)(b * 64 + pos) * 96 + c] = Av;
    size_t hb = (size_t)(b * 64 + pos) * 288;
    g_hcat[hb + c]       = Bv;
    g_hcat[hb + 96 + c]  = Cv;
    g_hcat[hb + 192 + c] = Dv;
}

// ---------------- conv 3x3 (288 -> 96) + bias + LeakyReLU(0.2) ---------------
__global__ __launch_bounds__(256) void k_conv(const float* __restrict__ cw,
                                              const float* __restrict__ cb) {
    extern __shared__ float sm[];
    float* Ssh = sm;              // [288][10*10] haloed input
    float* Wsh = sm + 288 * 100;  // [96][16*9] weight chunk
    int tid = threadIdx.x, b = blockIdx.x;
    for (int idx = tid; idx < 288 * 100; idx += 256) Ssh[idx] = 0.f;
    __syncthreads();
    const float* hin = g_hcat + (size_t)b * 64 * 288;
    for (int idx = tid; idx < 64 * 288; idx += 256) {
        int ci = idx % 288, pos = idx / 288;
        int y = pos >> 3, xx = pos & 7;
        Ssh[ci * 100 + (y + 1) * 10 + (xx + 1)] = hin[idx];
    }
    int pt = tid & 15, ct = tid >> 4;
    int py = pt >> 1, px = (pt & 1) * 4;   // 4 positions: (py, px..px+3)
    float acc[4][6] = {};
    for (int ci0 = 0; ci0 < 288; ci0 += 16) {
        __syncthreads();
        for (int idx = tid; idx < 96 * 144; idx += 256) {
            int co = idx / 144, rem = idx % 144;
            Wsh[idx] = cw[(size_t)co * 2592 + ci0 * 9 + rem];
        }
        __syncthreads();
        #pragma unroll 1
        for (int cil = 0; cil < 16; cil++) {
            const float* Sp = Ssh + (ci0 + cil) * 100 + py * 10 + px;
            const float* Wp = Wsh + ct * 6 * 144 + cil * 9;
            #pragma unroll
            for (int ky = 0; ky < 3; ky++) {
                #pragma unroll
                for (int kx = 0; kx < 3; kx++) {
                    float iv0 = Sp[ky * 10 + kx + 0];
                    float iv1 = Sp[ky * 10 + kx + 1];
                    float iv2 = Sp[ky * 10 + kx + 2];
                    float iv3 = Sp[ky * 10 + kx + 3];
                    #pragma unroll
                    for (int u = 0; u < 6; u++) {
                        float wv = Wp[u * 144 + ky * 3 + kx];
                        acc[0][u] += iv0 * wv; acc[1][u] += iv1 * wv;
                        acc[2][u] += iv2 * wv; acc[3][u] += iv3 * wv;
                    }
                }
            }
        }
    }
    float* outb = g_xh + (size_t)b * 64 * 96;
    #pragma unroll
    for (int u = 0; u < 6; u++) {
        int co = ct * 6 + u;
        float bv = cb[co];
        #pragma unroll
        for (int q = 0; q < 4; q++) {
            float v = acc[q][u] + bv;
            v = v >= 0.f ? v : 0.2f * v;
            outb[(pt * 4 + q) * 96 + co] = v;
        }
    }
}

// ---------------- kv projection + k l2norm + logit scale ---------------------
__global__ __launch_bounds__(256) void k_kv(int which, const float* __restrict__ w,
                                            const float* __restrict__ bias,
                                            const float* __restrict__ ls) {
    extern __shared__ float sm[];
    float* Ws = sm;             // [96 k][192 o]
    float* Xs = sm + 96 * 192;  // [64 r][96 k]
    const float* X = which ? g_xh : g_A;
    float* kb = g_k[which];
    float* vb = g_v[which];
    int tid = threadIdx.x;
    int row0 = blockIdx.x * 64;
    for (int idx = tid; idx < 192 * 96; idx += 256) {
        int k = idx % 96, o = idx / 96;
        Ws[k * 192 + o] = w[idx];
    }
    for (int idx = tid; idx < 64 * 96; idx += 256)
        Xs[idx] = X[(size_t)row0 * 96 + idx];
    __syncthreads();
    int lane = tid & 31, rg = tid >> 5;
    float acc[8][6] = {};
    const float* Xr = Xs + rg * 8 * 96;
    #pragma unroll 1
    for (int k4 = 0; k4 < 96; k4 += 4) {
        float4 xv[8];
        #pragma unroll
        for (int r = 0; r < 8; r++) xv[r] = *(const float4*)(Xr + r * 96 + k4);
        #pragma unroll
        for (int kk = 0; kk < 4; kk++) {
            float wv[6];
            #pragma unroll
            for (int j = 0; j < 6; j++) wv[j] = Ws[(k4 + kk) * 192 + lane + 32 * j];
            #pragma unroll
            for (int r = 0; r < 8; r++) {
                float xs = (&xv[r].x)[kk];
                #pragma unroll
                for (int j = 0; j < 6; j++) acc[r][j] += xs * wv[j];
            }
        }
    }
    float scl[3];
    #pragma unroll
    for (int h = 0; h < 3; h++) scl[h] = expf(fminf(ls[h], 4.605170185988091f));
    #pragma unroll
    for (int j = 0; j < 6; j++) {
        float bj = bias[lane + 32 * j];
        #pragma unroll
        for (int r = 0; r < 8; r++) {
            int row = row0 + rg * 8 + r;
            int b = row >> 6, t = row & 63;
            float v = acc[r][j] + bj;
            if (j < 3) {  // key half: l2norm over the 32 lanes of this chunk, then scale
                float ss = v * v;
                #pragma unroll
                for (int off = 16; off; off >>= 1) ss += __shfl_xor_sync(0xffffffffu, ss, off);
                v = v / fmaxf(sqrtf(ss), 1e-12f) * scl[j];
                kb[((size_t)(b * 3 + j) * 64 + t) * 32 + lane] = v;
            } else {
                vb[((size_t)(b * 3 + (j - 3)) * 64 + t) * 32 + lane] = v;
            }
        }
    }
}

// ---------------- attention: softmax(qn @ kn^T) @ v --------------------------
__global__ __launch_bounds__(256) void k_attn() {
    __shared__ float ksh[64 * 32];
    __shared__ float vsh[64 * 32];
    int bh = blockIdx.x;   // b*3 + h
    int br = blockIdx.y;   // branch (0 low, 1 high)
    int tid = threadIdx.x;
    const float* kb = g_k[br] + (size_t)bh * 2048;
    const float* vb = g_v[br] + (size_t)bh * 2048;
    for (int idx = tid; idx < 2048; idx += 256) { ksh[idx] = kb[idx]; vsh[idx] = vb[idx]; }
    __syncthreads();
    int b = bh / 3, h = bh % 3;
    int n = tid;
    float4 q4[8];
    const float* qp = g_qn + ((size_t)(b * 256 + n)) * 96 + h * 32;
    #pragma unroll
    for (int i = 0; i < 8; i++) q4[i] = *(const float4*)(qp + 4 * i);
    float s[64];
    float m = -1e30f;
    #pragma unroll 1
    for (int t = 0; t < 64; t++) {
        const float4* kr = (const float4*)(ksh + t * 32);
        float dot = 0.f;
        #pragma unroll
        for (int i = 0; i < 8; i++) {
            float4 kv4 = kr[i];
            dot += q4[i].x * kv4.x + q4[i].y * kv4.y + q4[i].z * kv4.z + q4[i].w * kv4.w;
        }
        s[t] = dot;
        m = fmaxf(m, dot);
    }
    float sum = 0.f;
    float4 o4[8];
    #pragma unroll
    for (int i = 0; i < 8; i++) o4[i] = make_float4(0.f, 0.f, 0.f, 0.f);
    #pragma unroll 1
    for (int t = 0; t < 64; t++) {
        float p = expf(s[t] - m);
        sum += p;
        const float4* vr = (const float4*)(vsh + t * 32);
        #pragma unroll
        for (int i = 0; i < 8; i++) {
            float4 vv = vr[i];
            o4[i].x += p * vv.x; o4[i].y += p * vv.y; o4[i].z += p * vv.z; o4[i].w += p * vv.w;
        }
    }
    float inv = 1.f / sum;
    float* op = g_attn[br] + ((size_t)bh * 256 + n) * 32;
    #pragma unroll
    for (int i = 0; i < 8; i++) {
        float4 ov = make_float4(o4[i].x * inv, o4[i].y * inv, o4[i].z * inv, o4[i].w * inv);
        *(float4*)(op + 4 * i) = ov;
    }
}

// ---------------- fused (fuse_lh + proj) GEMM over interleaved concat --------
__global__ __launch_bounds__(256) void k_fuse(float* __restrict__ out) {
    extern __shared__ float sm[];
    float* Ws = sm;              // [192 e][96 c2]
    float* Xs = sm + 192 * 96;   // [64 r][192 e]
    int tid = threadIdx.x;
    int row0 = blockIdx.x * 64;
    for (int idx = tid; idx < 96 * 192; idx += 256) {
        int e = idx % 192, c2 = idx / 192;
        Ws[e * 96 + c2] = g_Wc[idx];
    }
    // gather concat([a_low, a_high]) rows; e = br*96 + (dd*3 + h)
    for (int idx = tid; idx < 64 * 192; idx += 256) {
        int rloc = idx / 192, rem = idx % 192;
        int br = rem / 96, rem2 = rem % 96;
        int h = rem2 >> 5, dd = rem2 & 31;
        int row = row0 + rloc, b = row >> 8, n = row & 255;
        Xs[rloc * 192 + br * 96 + dd * 3 + h] =
            g_attn[br][(((size_t)(b * 3 + h)) * 256 + n) * 32 + dd];
    }
    __syncthreads();
    int lane = tid & 31, rg = tid >> 5;
    float acc[8][3] = {};
    const float* Xr = Xs + rg * 8 * 192;
    #pragma unroll 1
    for (int k4 = 0; k4 < 192; k4 += 4) {
        float4 xv[8];
        #pragma unroll
        for (int r = 0; r < 8; r++) xv[r] = *(const float4*)(Xr + r * 192 + k4);
        #pragma unroll
        for (int kk = 0; kk < 4; kk++) {
            float w0 = Ws[(k4 + kk) * 96 + lane];
            float w1 = Ws[(k4 + kk) * 96 + lane + 32];
            float w2 = Ws[(k4 + kk) * 96 + lane + 64];
            #pragma unroll
            for (int r = 0; r < 8; r++) {
                float xs = (&xv[r].x)[kk];
                acc[r][0] += xs * w0; acc[r][1] += xs * w1; acc[r][2] += xs * w2;
            }
        }
    }
    #pragma unroll
    for (int j = 0; j < 3; j++) {
        float bj = g_bc[lane + 32 * j];
        #pragma unroll
        for (int r = 0; r < 8; r++)
            out[(size_t)(row0 + rg * 8 + r) * 96 + lane + 32 * j] = acc[r][j] + bj;
    }
}

// ---------------------------------------------------------------------------
extern "C" void kernel_launch(void* const* d_in, const int* in_sizes, int n_in,
                              void* d_out, int out_size) {
    const float* x   = (const float*)d_in[0];
    const float* qw  = (const float*)d_in[1];
    const float* qb  = (const float*)d_in[2];
    const float* klw = (const float*)d_in[3];
    const float* klb = (const float*)d_in[4];
    const float* khw = (const float*)d_in[5];
    const float* khb = (const float*)d_in[6];
    const float* cw  = (const float*)d_in[7];
    const float* cb  = (const float*)d_in[8];
    const float* fw  = (const float*)d_in[9];
    const float* fb  = (const float*)d_in[10];
    const float* pw  = (const float*)d_in[11];
    const float* pb  = (const float*)d_in[12];
    const float* lsl = (const float*)d_in[13];
    const float* lsh = (const float*)d_in[14];
    float* out = (float*)d_out;

    const int smem_q    = (96 * 96 + 64 * 96) * 4;     // 61440
    const int smem_kv   = (96 * 192 + 64 * 96) * 4;    // 98304
    const int smem_conv = (288 * 100 + 96 * 144) * 4;  // 170496
    const int smem_fuse = (192 * 96 + 64 * 192) * 4;   // 122880
    cudaFuncSetAttribute(k_q,    cudaFuncAttributeMaxDynamicSharedMemorySize, smem_q);
    cudaFuncSetAttribute(k_kv,   cudaFuncAttributeMaxDynamicSharedMemorySize, smem_kv);
    cudaFuncSetAttribute(k_conv, cudaFuncAttributeMaxDynamicSharedMemorySize, smem_conv);
    cudaFuncSetAttribute(k_fuse, cudaFuncAttributeMaxDynamicSharedMemorySize, smem_fuse);

    k_combine<<<72, 256>>>(fw, fb, pw, pb);
    k_q<<<(Bn * Nn) / 64, 256, smem_q>>>(x, qw, qb);
    k_nlwt<<<(Bn * N4 * Cc) / 256, 256>>>(x);
    k_conv<<<Bn, 256, smem_conv>>>(cw, cb);
    k_kv<<<(Bn * N4) / 64, 256, smem_kv>>>(0, klw, klb, lsl);
    k_kv<<<(Bn * N4) / 64, 256, smem_kv>>>(1, khw, khb, lsh);
    k_attn<<<dim3(Bn * Hh, 2), 256>>>();
    k_fuse<<<(Bn * Nn) / 64, 256, smem_fuse>>>(out);
}

// round 2
// speedup vs baseline: 1.3870x; 1.3870x over previous
#include <cuda_runtime.h>
#include <math.h>

#define Bn 2048
#define Nn 256
#define Cc 96
#define Hh 3
#define Dd 32
#define N4 64
#define CI 288   // 3*C

typedef unsigned long long ull;

// packed f32x2 helpers (sm_103a)
#define FFMA2(d, a, b, c) \
    asm("fma.rn.f32x2 %0, %1, %2, %3;" : "=l"(d) : "l"(a), "l"(b), "l"(c))
#define DUPF2(d, s) \
    asm("mov.b64 %0, {%1, %1};" : "=l"(d) : "f"(s))
#define UNPK2(lo, hi, s) \
    asm("mov.b64 {%0, %1}, %2;" : "=f"(lo), "=f"(hi) : "l"(s))

// ---------------- scratch (device globals; no allocations allowed) ----------
__device__ float g_qn[(size_t)Bn*Nn*Cc];            // normalized q, (B,N,C)
__device__ float g_A [(size_t)Bn*N4*Cc];            // low-band tokens (B,64,C)
__device__ float g_hcat[(size_t)Bn*N4*CI];          // high subbands token-major (B,64,3C)
__device__ float g_xh[(size_t)Bn*N4*Cc];            // conv output token-major (B,64,C)
__device__ float g_k[2][(size_t)Bn*Hh*N4*Dd];       // normalized+scaled keys (B,H,64,32)
__device__ float g_v[2][(size_t)Bn*Hh*N4*Dd];       // values (B,H,64,32)
__device__ float g_attnL[(size_t)Bn*4*192*64];      // attn out, fuse-friendly layout
__device__ float g_WcT[192*Cc];                     // folded fuse+proj weight, [e][c2]
__device__ float g_bc[Cc];                          // folded bias
__device__ float g_cw2[2592*Cc];                    // conv weight re-layout [(ci*9+kk)][co]

// ---------------- fold proj @ fuse into one GEMM weight ---------------------
__global__ void k_combine(const float* __restrict__ fw, const float* __restrict__ fb,
                          const float* __restrict__ pw, const float* __restrict__ pb) {
    int gid = blockIdx.x * 256 + threadIdx.x;   // 96*192 = 18432 = 72 blocks
    if (gid < 96 * 192) {
        int c2 = gid / 192, e = gid % 192;
        float s = 0.f;
        #pragma unroll 4
        for (int c1 = 0; c1 < 96; c1++) s += pw[c2 * 96 + c1] * fw[c1 * 192 + e];
        g_WcT[e * 96 + c2] = s;
    }
    if (gid < 96) {
        float s = pb[gid];
        #pragma unroll 4
        for (int c1 = 0; c1 < 96; c1++) s += pw[gid * 96 + c1] * fb[c1];
        g_bc[gid] = s;
    }
}

// ---------------- conv weight re-layout (once per launch) --------------------
__global__ void k_wrearr(const float* __restrict__ cw) {
    int idx = blockIdx.x * 256 + threadIdx.x;   // 2592*96 = 248832
    if (idx < 2592 * 96) {
        int co = idx % 96, rest = idx / 96;
        g_cw2[(size_t)rest * 96 + co] = cw[(size_t)co * 2592 + rest];
    }
}

// ---------------- q = x @ q_w^T + b, per-head l2norm -------------------------
__global__ __launch_bounds__(256) void k_q(const float* __restrict__ x,
                                           const float* __restrict__ w,
                                           const float* __restrict__ bias) {
    extern __shared__ float sm[];
    float* Ws = sm;            // [96 k][96 o]
    float* Xs = sm + 96 * 96;  // [64 r][96 k]
    int tid = threadIdx.x;
    int row0 = blockIdx.x * 64;
    for (int idx = tid; idx < 96 * 96; idx += 256) {
        int k = idx % 96, o = idx / 96;
        Ws[k * 96 + o] = w[idx];
    }
    for (int idx = tid; idx < 64 * 96; idx += 256)
        Xs[idx] = x[(size_t)row0 * 96 + idx];
    __syncthreads();
    int lane = tid & 31, rg = tid >> 5;
    float acc[8][3];
    #pragma unroll
    for (int r = 0; r < 8; r++) { acc[r][0] = 0.f; acc[r][1] = 0.f; acc[r][2] = 0.f; }
    const float* Xr = Xs + rg * 8 * 96;
    #pragma unroll 1
    for (int k4 = 0; k4 < 96; k4 += 4) {
        float4 xv[8];
        #pragma unroll
        for (int r = 0; r < 8; r++) xv[r] = *(const float4*)(Xr + r * 96 + k4);
        #pragma unroll
        for (int kk = 0; kk < 4; kk++) {
            float w0 = Ws[(k4 + kk) * 96 + lane];
            float w1 = Ws[(k4 + kk) * 96 + lane + 32];
            float w2 = Ws[(k4 + kk) * 96 + lane + 64];
            #pragma unroll
            for (int r = 0; r < 8; r++) {
                float xs = (&xv[r].x)[kk];
                acc[r][0] += xs * w0; acc[r][1] += xs * w1; acc[r][2] += xs * w2;
            }
        }
    }
    #pragma unroll
    for (int j = 0; j < 3; j++) {
        float bj = bias[lane + 32 * j];
        #pragma unroll
        for (int r = 0; r < 8; r++) {
            float v = acc[r][j] + bj;
            float ss = v * v;
            #pragma unroll
            for (int off = 16; off; off >>= 1) ss += __shfl_xor_sync(0xffffffffu, ss, off);
            float inv = 1.0f / fmaxf(sqrtf(ss), 1e-12f);
            g_qn[(size_t)(row0 + rg * 8 + r) * 96 + lane + 32 * j] = v * inv;
        }
    }
}

// ---------------- NLWT: x (B,N,C as B,C,16,16) -> A + high concat ------------
__global__ __launch_bounds__(256) void k_nlwt(const float* __restrict__ x) {
    int gid = blockIdx.x * 256 + threadIdx.x;   // Bn*64*96 threads exactly
    int c = gid % 96;
    int pos = (gid / 96) & 63;
    int b = gid / (96 * 64);
    int i = pos >> 3, j = pos & 7;
    int i2 = (i + 1) & 7, j2 = (j + 1) & 7;
    const float* xb = x + (size_t)b * 256 * 96;
    #define LDX(yy, xx) xb[((yy) * 16 + (xx)) * 96 + c]
    float a0 = LDX(2*i, 2*j),  a1 = LDX(2*i, 2*j+1),  a2 = LDX(2*i+1, 2*j),  a3 = LDX(2*i+1, 2*j+1);
    float t0 =  0.8664f*a0 + 0.1026f*a1 + 0.4852f*a2 - 0.0574f*a3;
    float b0 = LDX(2*i2, 2*j), b1 = LDX(2*i2, 2*j+1), b2 = LDX(2*i2+1, 2*j), b3 = LDX(2*i2+1, 2*j+1);
    float t1 = -0.1026f*b0 + 0.8664f*b1 - 0.0574f*b2 - 0.4852f*b3;
    float c0 = LDX(2*i, 2*j2), c1 = LDX(2*i, 2*j2+1), c2 = LDX(2*i+1, 2*j2), c3 = LDX(2*i+1, 2*j2+1);
    float t2 =  0.4852f*c0 + 0.0574f*c1 - 0.8664f*c2 + 0.1026f*c3;
    float d0 = LDX(2*i2, 2*j2), d1 = LDX(2*i2, 2*j2+1), d2 = LDX(2*i2+1, 2*j2), d3 = LDX(2*i2+1, 2*j2+1);
    float t3 =  0.0574f*d0 - 0.4852f*d1 - 0.1026f*d2 - 0.8664f*d3;
    #undef LDX
    float Av =  1.3968f*t0 + 0.2212f*t1 - 0.2212f*t2 - 1.3968f*t3;
    float Bv = -0.2212f*t0 + 1.3968f*t1 - 1.3968f*t2 + 0.2212f*t3;
    float Cv = -0.5412f*t0 - 1.3066f*t1 - 1.3066f*t2 - 0.5412f*t3;
    float Dv =  1.3066f*t0 - 0.5412f*t1 - 0.5412f*t2 + 1.3066f*t3;
    g_A[(size_t)(b * 64 + pos) * 96 + c] = Av;
    size_t hb = (size_t)(b * 64 + pos) * 288;
    g_hcat[hb + c]       = Bv;
    g_hcat[hb + 96 + c]  = Cv;
    g_hcat[hb + 192 + c] = Dv;
}

// ------- conv 3x3 (288 -> 96) + bias + LeakyReLU(0.2), f32x2 over co-pairs ---
__global__ __launch_bounds__(256) void k_conv(const float* __restrict__ cb) {
    extern __shared__ float sm[];
    float* Ssh = sm;             // [288][10*10] haloed input
    float* Wsh = sm + 288 * 100; // [16 cil * 9 kk][96 co]
    int tid = threadIdx.x, b = blockIdx.x;
    for (int idx = tid; idx < 288 * 100; idx += 256) Ssh[idx] = 0.f;
    __syncthreads();
    const float* hin = g_hcat + (size_t)b * 64 * 288;
    for (int idx = tid; idx < 64 * 288; idx += 256) {
        int ci = idx % 288, pos = idx / 288;
        int y = pos >> 3, xx = pos & 7;
        Ssh[ci * 100 + (y + 1) * 10 + (xx + 1)] = hin[idx];
    }
    int pt = tid & 15, ct = tid >> 4;
    int py = pt >> 1, px = (pt & 1) * 4;   // 4 positions: (py, px..px+3)
    int co0 = ct * 6;                      // 6 output channels = 3 co-pairs
    ull acc2[4][3];
    #pragma unroll
    for (int p = 0; p < 4; p++) { acc2[p][0] = 0ull; acc2[p][1] = 0ull; acc2[p][2] = 0ull; }
    for (int ci0 = 0; ci0 < 288; ci0 += 16) {
        __syncthreads();
        for (int idx = tid; idx < 16 * 9 * 96; idx += 256)
            Wsh[idx] = g_cw2[(size_t)ci0 * 9 * 96 + idx];
        __syncthreads();
        #pragma unroll 1
        for (int cil = 0; cil < 16; cil++) {
            const float* Sp = Ssh + (ci0 + cil) * 100 + py * 10 + px;
            const float* Wp = Wsh + cil * 9 * 96 + co0;
            #pragma unroll
            for (int ky = 0; ky < 3; ky++) {
                ull d[6];
                #pragma unroll
                for (int j = 0; j < 6; j++) { float s = Sp[ky * 10 + j]; DUPF2(d[j], s); }
                #pragma unroll
                for (int kx = 0; kx < 3; kx++) {
                    const float* wrow = Wp + (ky * 3 + kx) * 96;
                    ull w0 = *(const ull*)(wrow);
                    ull w1 = *(const ull*)(wrow + 2);
                    ull w2 = *(const ull*)(wrow + 4);
                    #pragma unroll
                    for (int p = 0; p < 4; p++) {
                        FFMA2(acc2[p][0], d[p + kx], w0, acc2[p][0]);
                        FFMA2(acc2[p][1], d[p + kx], w1, acc2[p][1]);
                        FFMA2(acc2[p][2], d[p + kx], w2, acc2[p][2]);
                    }
                }
            }
        }
    }
    float* outb = g_xh + (size_t)b * 64 * 96;
    #pragma unroll
    for (int p = 0; p < 4; p++) {
        int pos = py * 8 + px + p;
        #pragma unroll
        for (int cp = 0; cp < 3; cp++) {
            float lo, hi; UNPK2(lo, hi, acc2[p][cp]);
            int co = co0 + 2 * cp;
            float v0 = lo + cb[co];     v0 = v0 >= 0.f ? v0 : 0.2f * v0;
            float v1 = hi + cb[co + 1]; v1 = v1 >= 0.f ? v1 : 0.2f * v1;
            outb[pos * 96 + co] = v0;
            outb[pos * 96 + co + 1] = v1;
        }
    }
}

// ---------------- kv projection + k l2norm + logit scale ---------------------
__global__ __launch_bounds__(256) void k_kv(int which, const float* __restrict__ w,
                                            const float* __restrict__ bias,
                                            const float* __restrict__ ls) {
    extern __shared__ float sm[];
    float* Ws = sm;             // [96 k][192 o]
    float* Xs = sm + 96 * 192;  // [64 r][96 k]
    const float* X = which ? g_xh : g_A;
    float* kb = g_k[which];
    float* vb = g_v[which];
    int tid = threadIdx.x;
    int row0 = blockIdx.x * 64;
    for (int idx = tid; idx < 192 * 96; idx += 256) {
        int k = idx % 96, o = idx / 96;
        Ws[k * 192 + o] = w[idx];
    }
    for (int idx = tid; idx < 64 * 96; idx += 256)
        Xs[idx] = X[(size_t)row0 * 96 + idx];
    __syncthreads();
    int lane = tid & 31, rg = tid >> 5;
    float acc[8][6] = {};
    const float* Xr = Xs + rg * 8 * 96;
    #pragma unroll 1
    for (int k4 = 0; k4 < 96; k4 += 4) {
        float4 xv[8];
        #pragma unroll
        for (int r = 0; r < 8; r++) xv[r] = *(const float4*)(Xr + r * 96 + k4);
        #pragma unroll
        for (int kk = 0; kk < 4; kk++) {
            float wv[6];
            #pragma unroll
            for (int j = 0; j < 6; j++) wv[j] = Ws[(k4 + kk) * 192 + lane + 32 * j];
            #pragma unroll
            for (int r = 0; r < 8; r++) {
                float xs = (&xv[r].x)[kk];
                #pragma unroll
                for (int j = 0; j < 6; j++) acc[r][j] += xs * wv[j];
            }
        }
    }
    float scl[3];
    #pragma unroll
    for (int h = 0; h < 3; h++) scl[h] = expf(fminf(ls[h], 4.605170185988091f));
    #pragma unroll
    for (int j = 0; j < 6; j++) {
        float bj = bias[lane + 32 * j];
        #pragma unroll
        for (int r = 0; r < 8; r++) {
            int row = row0 + rg * 8 + r;
            int b = row >> 6, t = row & 63;
            float v = acc[r][j] + bj;
            if (j < 3) {
                float ss = v * v;
                #pragma unroll
                for (int off = 16; off; off >>= 1) ss += __shfl_xor_sync(0xffffffffu, ss, off);
                v = v / fmaxf(sqrtf(ss), 1e-12f) * scl[j];
                kb[((size_t)(b * 3 + j) * 64 + t) * 32 + lane] = v;
            } else {
                vb[((size_t)(b * 3 + (j - 3)) * 64 + t) * 32 + lane] = v;
            }
        }
    }
}

// ---------------- attention: softmax(qn @ kn^T) @ v, f32x2 over d ------------
__global__ __launch_bounds__(256) void k_attn() {
    __shared__ __align__(16) float ksh[64 * 32];
    __shared__ __align__(16) float vsh[64 * 32];
    int bh = blockIdx.x;   // b*3 + h
    int br = blockIdx.y;   // branch (0 low, 1 high)
    int tid = threadIdx.x;
    const float* kb = g_k[br] + (size_t)bh * 2048;
    const float* vb = g_v[br] + (size_t)bh * 2048;
    for (int idx = tid; idx < 2048; idx += 256) { ksh[idx] = kb[idx]; vsh[idx] = vb[idx]; }
    __syncthreads();
    int b = bh / 3, h = bh % 3;
    int n = tid;
    ull q2[16];
    const float* qp = g_qn + ((size_t)(b * 256 + n)) * 96 + h * 32;
    const ulonglong2* qp2 = (const ulonglong2*)qp;   // 128B aligned
    #pragma unroll
    for (int i = 0; i < 8; i++) { ulonglong2 t = qp2[i]; q2[2*i] = t.x; q2[2*i+1] = t.y; }
    float s[64];
    float m = -1e30f;
    #pragma unroll 1
    for (int t = 0; t < 64; t++) {
        const ull* kr = (const ull*)(ksh + t * 32);
        ull a0 = 0ull, a1 = 0ull;
        #pragma unroll
        for (int i = 0; i < 16; i += 2) {
            FFMA2(a0, q2[i],     kr[i],     a0);
            FFMA2(a1, q2[i + 1], kr[i + 1], a1);
        }
        float l0, h0, l1, h1;
        UNPK2(l0, h0, a0); UNPK2(l1, h1, a1);
        float dot = (l0 + h0) + (l1 + h1);
        s[t] = dot;
        m = fmaxf(m, dot);
    }
    float sum = 0.f;
    ull o2[16];
    #pragma unroll
    for (int i = 0; i < 16; i++) o2[i] = 0ull;
    #pragma unroll 1
    for (int t = 0; t < 64; t++) {
        float p = expf(s[t] - m);
        sum += p;
        ull pd; DUPF2(pd, p);
        const ull* vr = (const ull*)(vsh + t * 32);
        #pragma unroll
        for (int i = 0; i < 16; i++) FFMA2(o2[i], pd, vr[i], o2[i]);
    }
    float inv = 1.f / sum;
    // write layout: g_attnL[((b*4 + nblk)*192 + br*96 + dd*3 + h)*64 + r]
    size_t base = (((size_t)(b * 4 + (n >> 6)) * 192) + br * 96 + h) * 64 + (n & 63);
    #pragma unroll
    for (int i = 0; i < 16; i++) {
        float lo, hi; UNPK2(lo, hi, o2[i]);
        g_attnL[base + (size_t)(2 * i) * 192]     = lo * inv;
        g_attnL[base + (size_t)(2 * i + 1) * 192] = hi * inv;
    }
}

// ---------------- fused (fuse_lh + proj) GEMM, f32x2 over row pairs ----------
__global__ __launch_bounds__(256) void k_fuse(float* __restrict__ out) {
    extern __shared__ float sm[];
    float* Ws = sm;              // [192 e][96 c2]
    float* Xs = sm + 192 * 96;   // [192 e][32 r]
    int tid = threadIdx.x;
    int blk = blockIdx.x;        // 16384
    int b = blk >> 3;
    int n0 = (blk & 7) * 32;
    int nblk = n0 >> 6, r0 = n0 & 63;
    const float* src = g_attnL + ((size_t)(b * 4 + nblk) * 192) * 64;
    for (int idx = tid; idx < 192 * 96; idx += 256) Ws[idx] = g_WcT[idx];
    for (int idx = tid; idx < 192 * 32; idx += 256) {
        int e = idx >> 5, r = idx & 31;
        Xs[idx] = src[e * 64 + r0 + r];
    }
    __syncthreads();
    int lane = tid & 31, rg = tid >> 5;   // rg covers rows rg*4 .. rg*4+3 (2 pairs)
    ull acc2[2][3];
    #pragma unroll
    for (int p = 0; p < 2; p++) { acc2[p][0] = 0ull; acc2[p][1] = 0ull; acc2[p][2] = 0ull; }
    #pragma unroll 2
    for (int e = 0; e < 192; e++) {
        float w0 = Ws[e * 96 + lane];
        float w1 = Ws[e * 96 + lane + 32];
        float w2 = Ws[e * 96 + lane + 64];
        ull wd0, wd1, wd2;
        DUPF2(wd0, w0); DUPF2(wd1, w1); DUPF2(wd2, w2);
        ull x0 = *(const ull*)(Xs + e * 32 + rg * 4);
        ull x1 = *(const ull*)(Xs + e * 32 + rg * 4 + 2);
        FFMA2(acc2[0][0], x0, wd0, acc2[0][0]);
        FFMA2(acc2[0][1], x0, wd1, acc2[0][1]);
        FFMA2(acc2[0][2], x0, wd2, acc2[0][2]);
        FFMA2(acc2[1][0], x1, wd0, acc2[1][0]);
        FFMA2(acc2[1][1], x1, wd1, acc2[1][1]);
        FFMA2(acc2[1][2], x1, wd2, acc2[1][2]);
    }
    float bv0 = g_bc[lane], bv1 = g_bc[lane + 32], bv2 = g_bc[lane + 64];
    #pragma unroll
    for (int p = 0; p < 2; p++) {
        size_t row = (size_t)b * 256 + n0 + rg * 4 + p * 2;
        float lo, hi;
        UNPK2(lo, hi, acc2[p][0]);
        out[row * 96 + lane] = lo + bv0;       out[(row + 1) * 96 + lane] = hi + bv0;
        UNPK2(lo, hi, acc2[p][1]);
        out[row * 96 + lane + 32] = lo + bv1;  out[(row + 1) * 96 + lane + 32] = hi + bv1;
        UNPK2(lo, hi, acc2[p][2]);
        out[row * 96 + lane + 64] = lo + bv2;  out[(row + 1) * 96 + lane + 64] = hi + bv2;
    }
}

// ---------------------------------------------------------------------------
extern "C" void kernel_launch(void* const* d_in, const int* in_sizes, int n_in,
                              void* d_out, int out_size) {
    const float* x   = (const float*)d_in[0];
    const float* qw  = (const float*)d_in[1];
    const float* qb  = (const float*)d_in[2];
    const float* klw = (const float*)d_in[3];
    const float* klb = (const float*)d_in[4];
    const float* khw = (const float*)d_in[5];
    const float* khb = (const float*)d_in[6];
    const float* cw  = (const float*)d_in[7];
    const float* cb  = (const float*)d_in[8];
    const float* fw  = (const float*)d_in[9];
    const float* fb  = (const float*)d_in[10];
    const float* pw  = (const float*)d_in[11];
    const float* pb  = (const float*)d_in[12];
    const float* lsl = (const float*)d_in[13];
    const float* lsh = (const float*)d_in[14];
    float* out = (float*)d_out;

    const int smem_q    = (96 * 96 + 64 * 96) * 4;     // 61440
    const int smem_kv   = (96 * 192 + 64 * 96) * 4;    // 98304
    const int smem_conv = (288 * 100 + 16 * 9 * 96) * 4; // 170496
    const int smem_fuse = (192 * 96 + 192 * 32) * 4;   // 98304
    cudaFuncSetAttribute(k_q,    cudaFuncAttributeMaxDynamicSharedMemorySize, smem_q);
    cudaFuncSetAttribute(k_kv,   cudaFuncAttributeMaxDynamicSharedMemorySize, smem_kv);
    cudaFuncSetAttribute(k_conv, cudaFuncAttributeMaxDynamicSharedMemorySize, smem_conv);
    cudaFuncSetAttribute(k_fuse, cudaFuncAttributeMaxDynamicSharedMemorySize, smem_fuse);

    k_combine<<<72, 256>>>(fw, fb, pw, pb);
    k_wrearr<<<972, 256>>>(cw);
    k_q<<<(Bn * Nn) / 64, 256, smem_q>>>(x, qw, qb);
    k_nlwt<<<(Bn * N4 * Cc) / 256, 256>>>(x);
    k_conv<<<Bn, 256, smem_conv>>>(cb);
    k_kv<<<(Bn * N4) / 64, 256, smem_kv>>>(0, klw, klb, lsl);
    k_kv<<<(Bn * N4) / 64, 256, smem_kv>>>(1, khw, khb, lsh);
    k_attn<<<dim3(Bn * Hh, 2), 256>>>();
    k_fuse<<<Bn * 8, 256, smem_fuse>>>(out);
}

// round 3
// speedup vs baseline: 1.6497x; 1.1894x over previous
#include <cuda_runtime.h>
#include <math.h>

#define Bn 2048
#define Nn 256
#define Cc 96
#define Hh 3
#define Dd 32
#define N4 64
#define CI 288   // 3*C

typedef unsigned long long ull;

// packed f32x2 helpers (sm_103a)
#define FFMA2(d, a, b, c) \
    asm("fma.rn.f32x2 %0, %1, %2, %3;" : "=l"(d) : "l"(a), "l"(b), "l"(c))
#define DUPF2(d, s) \
    asm("mov.b64 %0, {%1, %1};" : "=l"(d) : "f"(s))
#define UNPK2(lo, hi, s) \
    asm("mov.b64 {%0, %1}, %2;" : "=f"(lo), "=f"(hi) : "l"(s))

// ---------------- scratch (device globals; no allocations allowed) ----------
__device__ float g_qn[(size_t)Bn*Nn*Cc];            // normalized q, (B,N,C)
__device__ float g_A [(size_t)Bn*N4*Cc];            // low-band tokens (B,64,C)
__device__ float g_hcat[(size_t)Bn*N4*CI];          // high subbands token-major (B,64,3C)
__device__ float g_xh[(size_t)Bn*N4*Cc];            // conv output token-major (B,64,C)
__device__ float g_k[2][(size_t)Bn*Hh*N4*Dd];       // normalized+scaled keys (B,H,64,32)
__device__ float g_v[2][(size_t)Bn*Hh*N4*Dd];       // values (B,H,64,32)
__device__ float g_attnL[(size_t)Bn*4*192*64];      // attn out, fuse-friendly layout
__device__ float g_WcT[192*Cc];                     // folded fuse+proj weight, [e][c2]
__device__ float g_bc[Cc];                          // folded bias
__device__ float g_cw2[2592*Cc];                    // conv weight re-layout [(ci*9+kk)][co]

// ---------------- fold proj @ fuse into one GEMM weight ---------------------
__global__ void k_combine(const float* __restrict__ fw, const float* __restrict__ fb,
                          const float* __restrict__ pw, const float* __restrict__ pb) {
    int gid = blockIdx.x * 256 + threadIdx.x;
    if (gid < 96 * 192) {
        int c2 = gid / 192, e = gid % 192;
        float s = 0.f;
        #pragma unroll 4
        for (int c1 = 0; c1 < 96; c1++) s += pw[c2 * 96 + c1] * fw[c1 * 192 + e];
        g_WcT[e * 96 + c2] = s;
    }
    if (gid < 96) {
        float s = pb[gid];
        #pragma unroll 4
        for (int c1 = 0; c1 < 96; c1++) s += pw[gid * 96 + c1] * fb[c1];
        g_bc[gid] = s;
    }
}

// ---------------- conv weight re-layout (once per launch) --------------------
__global__ void k_wrearr(const float* __restrict__ cw) {
    int idx = blockIdx.x * 256 + threadIdx.x;
    if (idx < 2592 * 96) {
        int co = idx % 96, rest = idx / 96;
        g_cw2[(size_t)rest * 96 + co] = cw[(size_t)co * 2592 + rest];
    }
}

// ------- q = x @ q_w^T + b, per-head l2norm; FFMA2 over row pairs ------------
__global__ __launch_bounds__(256) void k_q(const float* __restrict__ x,
                                           const float* __restrict__ w,
                                           const float* __restrict__ bias) {
    extern __shared__ float sm[];
    float* Ws = sm;            // [96 k][96 o]
    float* Xs = sm + 96 * 96;  // [96 k][66 pitch r]
    int tid = threadIdx.x;
    int row0 = blockIdx.x * 64;
    for (int idx = tid; idx < 96 * 96; idx += 256) {
        int k = idx % 96, o = idx / 96;
        Ws[k * 96 + o] = w[idx];
    }
    for (int idx = tid; idx < 64 * 96; idx += 256) {
        int r = idx / 96, k = idx % 96;
        Xs[k * 66 + r] = x[(size_t)row0 * 96 + idx];
    }
    __syncthreads();
    int lane = tid & 31, rg = tid >> 5;
    ull acc2[4][3];
    #pragma unroll
    for (int p = 0; p < 4; p++) { acc2[p][0] = 0; acc2[p][1] = 0; acc2[p][2] = 0; }
    #pragma unroll 4
    for (int k = 0; k < 96; k++) {
        ull wd[3];
        #pragma unroll
        for (int j = 0; j < 3; j++) { float wv = Ws[k * 96 + lane + 32 * j]; DUPF2(wd[j], wv); }
        const float* xr = Xs + k * 66 + rg * 8;
        #pragma unroll
        for (int p = 0; p < 4; p++) {
            ull xp = *(const ull*)(xr + 2 * p);
            FFMA2(acc2[p][0], xp, wd[0], acc2[p][0]);
            FFMA2(acc2[p][1], xp, wd[1], acc2[p][1]);
            FFMA2(acc2[p][2], xp, wd[2], acc2[p][2]);
        }
    }
    #pragma unroll
    for (int j = 0; j < 3; j++) {
        float bj = bias[lane + 32 * j];
        #pragma unroll
        for (int p = 0; p < 4; p++) {
            float lo, hi; UNPK2(lo, hi, acc2[p][j]);
            #pragma unroll
            for (int e = 0; e < 2; e++) {
                float v = (e ? hi : lo) + bj;
                float ss = v * v;
                #pragma unroll
                for (int off = 16; off; off >>= 1) ss += __shfl_xor_sync(0xffffffffu, ss, off);
                float inv = 1.0f / fmaxf(sqrtf(ss), 1e-12f);
                g_qn[(size_t)(row0 + rg * 8 + 2 * p + e) * 96 + lane + 32 * j] = v * inv;
            }
        }
    }
}

// ---------------- NLWT: x (B,N,C as B,C,16,16) -> A + high concat ------------
__global__ __launch_bounds__(256) void k_nlwt(const float* __restrict__ x) {
    int gid = blockIdx.x * 256 + threadIdx.x;
    int c = gid % 96;
    int pos = (gid / 96) & 63;
    int b = gid / (96 * 64);
    int i = pos >> 3, j = pos & 7;
    int i2 = (i + 1) & 7, j2 = (j + 1) & 7;
    const float* xb = x + (size_t)b * 256 * 96;
    #define LDX(yy, xx) xb[((yy) * 16 + (xx)) * 96 + c]
    float a0 = LDX(2*i, 2*j),  a1 = LDX(2*i, 2*j+1),  a2 = LDX(2*i+1, 2*j),  a3 = LDX(2*i+1, 2*j+1);
    float t0 =  0.8664f*a0 + 0.1026f*a1 + 0.4852f*a2 - 0.0574f*a3;
    float b0 = LDX(2*i2, 2*j), b1 = LDX(2*i2, 2*j+1), b2 = LDX(2*i2+1, 2*j), b3 = LDX(2*i2+1, 2*j+1);
    float t1 = -0.1026f*b0 + 0.8664f*b1 - 0.0574f*b2 - 0.4852f*b3;
    float c0 = LDX(2*i, 2*j2), c1 = LDX(2*i, 2*j2+1), c2 = LDX(2*i+1, 2*j2), c3 = LDX(2*i+1, 2*j2+1);
    float t2 =  0.4852f*c0 + 0.0574f*c1 - 0.8664f*c2 + 0.1026f*c3;
    float d0 = LDX(2*i2, 2*j2), d1 = LDX(2*i2, 2*j2+1), d2 = LDX(2*i2+1, 2*j2), d3 = LDX(2*i2+1, 2*j2+1);
    float t3 =  0.0574f*d0 - 0.4852f*d1 - 0.1026f*d2 - 0.8664f*d3;
    #undef LDX
    float Av =  1.3968f*t0 + 0.2212f*t1 - 0.2212f*t2 - 1.3968f*t3;
    float Bv = -0.2212f*t0 + 1.3968f*t1 - 1.3968f*t2 + 0.2212f*t3;
    float Cv = -0.5412f*t0 - 1.3066f*t1 - 1.3066f*t2 - 0.5412f*t3;
    float Dv =  1.3066f*t0 - 0.5412f*t1 - 0.5412f*t2 + 1.3066f*t3;
    g_A[(size_t)(b * 64 + pos) * 96 + c] = Av;
    size_t hb = (size_t)(b * 64 + pos) * 288;
    g_hcat[hb + c]       = Bv;
    g_hcat[hb + 96 + c]  = Cv;
    g_hcat[hb + 192 + c] = Dv;
}

// ------- conv 3x3 (288->96) + LeakyReLU, f32x2, chunked input (3 CTA/SM) -----
__global__ __launch_bounds__(256) void k_conv(const float* __restrict__ cb) {
    extern __shared__ float sm[];
    float* Sch = sm;            // [16 cil][10*10] haloed input chunk
    float* Wsh = sm + 1600;     // [16 cil * 9 kk][96 co]
    int tid = threadIdx.x, b = blockIdx.x;
    // zero halo once (interior rewritten every chunk)
    for (int idx = tid; idx < 16 * 36; idx += 256) {
        int cil = idx / 36, j = idx % 36;
        int y, xx;
        if (j < 10)       { y = 0; xx = j; }
        else if (j < 20)  { y = 9; xx = j - 10; }
        else { int jj = j - 20; y = 1 + (jj >> 1); xx = (jj & 1) * 9; }
        Sch[cil * 100 + y * 10 + xx] = 0.f;
    }
    const float* hin = g_hcat + (size_t)b * 64 * 288;
    int pt = tid & 15, ct = tid >> 4;
    int py = pt >> 1, px = (pt & 1) * 4;
    int co0 = ct * 6;
    ull acc2[4][3];
    #pragma unroll
    for (int p = 0; p < 4; p++) { acc2[p][0] = 0; acc2[p][1] = 0; acc2[p][2] = 0; }
    for (int ci0 = 0; ci0 < 288; ci0 += 16) {
        __syncthreads();
        for (int idx = tid; idx < 1024; idx += 256) {
            int pos = idx >> 4, cil = idx & 15;
            int y = pos >> 3, xx = pos & 7;
            Sch[cil * 100 + (y + 1) * 10 + xx + 1] = hin[pos * 288 + ci0 + cil];
        }
        for (int idx = tid; idx < 16 * 9 * 96; idx += 256)
            Wsh[idx] = g_cw2[(size_t)ci0 * 9 * 96 + idx];
        __syncthreads();
        #pragma unroll 1
        for (int cil = 0; cil < 16; cil++) {
            const float* Sp = Sch + cil * 100 + py * 10 + px;
            const float* Wp = Wsh + cil * 9 * 96 + co0;
            #pragma unroll
            for (int ky = 0; ky < 3; ky++) {
                ull d[6];
                #pragma unroll
                for (int j = 0; j < 6; j++) { float s = Sp[ky * 10 + j]; DUPF2(d[j], s); }
                #pragma unroll
                for (int kx = 0; kx < 3; kx++) {
                    const float* wrow = Wp + (ky * 3 + kx) * 96;
                    ull w0 = *(const ull*)(wrow);
                    ull w1 = *(const ull*)(wrow + 2);
                    ull w2 = *(const ull*)(wrow + 4);
                    #pragma unroll
                    for (int p = 0; p < 4; p++) {
                        FFMA2(acc2[p][0], d[p + kx], w0, acc2[p][0]);
                        FFMA2(acc2[p][1], d[p + kx], w1, acc2[p][1]);
                        FFMA2(acc2[p][2], d[p + kx], w2, acc2[p][2]);
                    }
                }
            }
        }
    }
    float* outb = g_xh + (size_t)b * 64 * 96;
    #pragma unroll
    for (int p = 0; p < 4; p++) {
        int pos = py * 8 + px + p;
        #pragma unroll
        for (int cp = 0; cp < 3; cp++) {
            float lo, hi; UNPK2(lo, hi, acc2[p][cp]);
            int co = co0 + 2 * cp;
            float v0 = lo + cb[co];     v0 = v0 >= 0.f ? v0 : 0.2f * v0;
            float v1 = hi + cb[co + 1]; v1 = v1 >= 0.f ? v1 : 0.2f * v1;
            outb[pos * 96 + co] = v0;
            outb[pos * 96 + co + 1] = v1;
        }
    }
}

// ------- kv projection + k l2norm + logit scale; FFMA2 over row pairs --------
__global__ __launch_bounds__(256) void k_kv(int which, const float* __restrict__ w,
                                            const float* __restrict__ bias,
                                            const float* __restrict__ ls) {
    extern __shared__ float sm[];
    float* Ws = sm;             // [96 k][192 o]
    float* Xs = sm + 96 * 192;  // [96 k][66 pitch r]
    const float* X = which ? g_xh : g_A;
    float* kb = g_k[which];
    float* vb = g_v[which];
    int tid = threadIdx.x;
    int row0 = blockIdx.x * 64;
    for (int idx = tid; idx < 192 * 96; idx += 256) {
        int k = idx % 96, o = idx / 96;
        Ws[k * 192 + o] = w[idx];
    }
    for (int idx = tid; idx < 64 * 96; idx += 256) {
        int r = idx / 96, k = idx % 96;
        Xs[k * 66 + r] = X[(size_t)row0 * 96 + idx];
    }
    __syncthreads();
    int lane = tid & 31, rg = tid >> 5;
    ull acc2[4][6];
    #pragma unroll
    for (int p = 0; p < 4; p++)
        #pragma unroll
        for (int j = 0; j < 6; j++) acc2[p][j] = 0;
    #pragma unroll 2
    for (int k = 0; k < 96; k++) {
        ull wd[6];
        #pragma unroll
        for (int j = 0; j < 6; j++) { float wv = Ws[k * 192 + lane + 32 * j]; DUPF2(wd[j], wv); }
        const float* xr = Xs + k * 66 + rg * 8;
        #pragma unroll
        for (int p = 0; p < 4; p++) {
            ull xp = *(const ull*)(xr + 2 * p);
            #pragma unroll
            for (int j = 0; j < 6; j++) FFMA2(acc2[p][j], xp, wd[j], acc2[p][j]);
        }
    }
    float scl[3];
    #pragma unroll
    for (int h = 0; h < 3; h++) scl[h] = expf(fminf(ls[h], 4.605170185988091f));
    #pragma unroll
    for (int j = 0; j < 6; j++) {
        float bj = bias[lane + 32 * j];
        #pragma unroll
        for (int p = 0; p < 4; p++) {
            float lo, hi; UNPK2(lo, hi, acc2[p][j]);
            #pragma unroll
            for (int e = 0; e < 2; e++) {
                int row = row0 + rg * 8 + 2 * p + e;
                int b = row >> 6, t = row & 63;
                float v = (e ? hi : lo) + bj;
                if (j < 3) {
                    float ss = v * v;
                    #pragma unroll
                    for (int off = 16; off; off >>= 1) ss += __shfl_xor_sync(0xffffffffu, ss, off);
                    v = v / fmaxf(sqrtf(ss), 1e-12f) * scl[j];
                    kb[((size_t)(b * 3 + j) * 64 + t) * 32 + lane] = v;
                } else {
                    vb[((size_t)(b * 3 + (j - 3)) * 64 + t) * 32 + lane] = v;
                }
            }
        }
    }
}

// ------- attention: softmax(qn @ kn^T) @ v, f32x2; scores in smem ------------
__global__ __launch_bounds__(256, 2) void k_attn() {
    extern __shared__ float asm_[];
    float* ksh = asm_;            // 2048
    float* vsh = asm_ + 2048;     // 2048
    float* ssm = asm_ + 4096;     // 64*256
    int bh = blockIdx.x;   // b*3 + h
    int br = blockIdx.y;   // branch (0 low, 1 high)
    int tid = threadIdx.x;
    const float* kb = g_k[br] + (size_t)bh * 2048;
    const float* vb = g_v[br] + (size_t)bh * 2048;
    for (int idx = tid; idx < 2048; idx += 256) { ksh[idx] = kb[idx]; vsh[idx] = vb[idx]; }
    __syncthreads();
    int b = bh / 3, h = bh % 3;
    int n = tid;
    ull q2[16];
    const float* qp = g_qn + ((size_t)(b * 256 + n)) * 96 + h * 32;
    const ulonglong2* qp2 = (const ulonglong2*)qp;
    #pragma unroll
    for (int i = 0; i < 8; i++) { ulonglong2 t = qp2[i]; q2[2*i] = t.x; q2[2*i+1] = t.y; }
    float m = -1e30f;
    #pragma unroll 1
    for (int t = 0; t < 64; t++) {
        const ull* kr = (const ull*)(ksh + t * 32);
        ull a0 = 0ull, a1 = 0ull;
        #pragma unroll
        for (int i = 0; i < 16; i += 2) {
            FFMA2(a0, q2[i],     kr[i],     a0);
            FFMA2(a1, q2[i + 1], kr[i + 1], a1);
        }
        float l0, h0, l1, h1;
        UNPK2(l0, h0, a0); UNPK2(l1, h1, a1);
        float dot = (l0 + h0) + (l1 + h1);
        ssm[t * 256 + tid] = dot;
        m = fmaxf(m, dot);
    }
    float sum = 0.f;
    ull o2[16];
    #pragma unroll
    for (int i = 0; i < 16; i++) o2[i] = 0ull;
    #pragma unroll 1
    for (int t = 0; t < 64; t++) {
        float p = expf(ssm[t * 256 + tid] - m);
        sum += p;
        ull pd; DUPF2(pd, p);
        const ull* vr = (const ull*)(vsh + t * 32);
        #pragma unroll
        for (int i = 0; i < 16; i++) FFMA2(o2[i], pd, vr[i], o2[i]);
    }
    float inv = 1.f / sum;
    size_t base = (((size_t)(b * 4 + (n >> 6)) * 192) + br * 96 + h) * 64 + (n & 63);
    #pragma unroll
    for (int i = 0; i < 16; i++) {
        float lo, hi; UNPK2(lo, hi, o2[i]);
        g_attnL[base + (size_t)(2 * i) * 192]     = lo * inv;
        g_attnL[base + (size_t)(2 * i + 1) * 192] = hi * inv;
    }
}

// ---------------- fused (fuse_lh + proj) GEMM, f32x2 over row pairs ----------
__global__ __launch_bounds__(256) void k_fuse(float* __restrict__ out) {
    extern __shared__ float sm[];
    float* Ws = sm;              // [192 e][96 c2]
    float* Xs = sm + 192 * 96;   // [192 e][32 r]
    int tid = threadIdx.x;
    int blk = blockIdx.x;
    int b = blk >> 3;
    int n0 = (blk & 7) * 32;
    int nblk = n0 >> 6, r0 = n0 & 63;
    const float* src = g_attnL + ((size_t)(b * 4 + nblk) * 192) * 64;
    for (int idx = tid; idx < 192 * 96; idx += 256) Ws[idx] = g_WcT[idx];
    for (int idx = tid; idx < 192 * 32; idx += 256) {
        int e = idx >> 5, r = idx & 31;
        Xs[idx] = src[e * 64 + r0 + r];
    }
    __syncthreads();
    int lane = tid & 31, rg = tid >> 5;
    ull acc2[2][3];
    #pragma unroll
    for (int p = 0; p < 2; p++) { acc2[p][0] = 0; acc2[p][1] = 0; acc2[p][2] = 0; }
    #pragma unroll 2
    for (int e = 0; e < 192; e++) {
        float w0 = Ws[e * 96 + lane];
        float w1 = Ws[e * 96 + lane + 32];
        float w2 = Ws[e * 96 + lane + 64];
        ull wd0, wd1, wd2;
        DUPF2(wd0, w0); DUPF2(wd1, w1); DUPF2(wd2, w2);
        ull x0 = *(const ull*)(Xs + e * 32 + rg * 4);
        ull x1 = *(const ull*)(Xs + e * 32 + rg * 4 + 2);
        FFMA2(acc2[0][0], x0, wd0, acc2[0][0]);
        FFMA2(acc2[0][1], x0, wd1, acc2[0][1]);
        FFMA2(acc2[0][2], x0, wd2, acc2[0][2]);
        FFMA2(acc2[1][0], x1, wd0, acc2[1][0]);
        FFMA2(acc2[1][1], x1, wd1, acc2[1][1]);
        FFMA2(acc2[1][2], x1, wd2, acc2[1][2]);
    }
    float bv0 = g_bc[lane], bv1 = g_bc[lane + 32], bv2 = g_bc[lane + 64];
    #pragma unroll
    for (int p = 0; p < 2; p++) {
        size_t row = (size_t)b * 256 + n0 + rg * 4 + p * 2;
        float lo, hi;
        UNPK2(lo, hi, acc2[p][0]);
        out[row * 96 + lane] = lo + bv0;       out[(row + 1) * 96 + lane] = hi + bv0;
        UNPK2(lo, hi, acc2[p][1]);
        out[row * 96 + lane + 32] = lo + bv1;  out[(row + 1) * 96 + lane + 32] = hi + bv1;
        UNPK2(lo, hi, acc2[p][2]);
        out[row * 96 + lane + 64] = lo + bv2;  out[(row + 1) * 96 + lane + 64] = hi + bv2;
    }
}

// ---------------------------------------------------------------------------
extern "C" void kernel_launch(void* const* d_in, const int* in_sizes, int n_in,
                              void* d_out, int out_size) {
    const float* x   = (const float*)d_in[0];
    const float* qw  = (const float*)d_in[1];
    const float* qb  = (const float*)d_in[2];
    const float* klw = (const float*)d_in[3];
    const float* klb = (const float*)d_in[4];
    const float* khw = (const float*)d_in[5];
    const float* khb = (const float*)d_in[6];
    const float* cw  = (const float*)d_in[7];
    const float* cb  = (const float*)d_in[8];
    const float* fw  = (const float*)d_in[9];
    const float* fb  = (const float*)d_in[10];
    const float* pw  = (const float*)d_in[11];
    const float* pb  = (const float*)d_in[12];
    const float* lsl = (const float*)d_in[13];
    const float* lsh = (const float*)d_in[14];
    float* out = (float*)d_out;

    const int smem_q    = (96 * 96 + 96 * 66) * 4;       // 62208
    const int smem_kv   = (96 * 192 + 96 * 66) * 4;      // 99072
    const int smem_conv = (1600 + 16 * 9 * 96) * 4;      // 61696
    const int smem_attn = (2048 + 2048 + 64 * 256) * 4;  // 81920
    const int smem_fuse = (192 * 96 + 192 * 32) * 4;     // 98304
    cudaFuncSetAttribute(k_q,    cudaFuncAttributeMaxDynamicSharedMemorySize, smem_q);
    cudaFuncSetAttribute(k_kv,   cudaFuncAttributeMaxDynamicSharedMemorySize, smem_kv);
    cudaFuncSetAttribute(k_conv, cudaFuncAttributeMaxDynamicSharedMemorySize, smem_conv);
    cudaFuncSetAttribute(k_attn, cudaFuncAttributeMaxDynamicSharedMemorySize, smem_attn);
    cudaFuncSetAttribute(k_fuse, cudaFuncAttributeMaxDynamicSharedMemorySize, smem_fuse);

    k_combine<<<72, 256>>>(fw, fb, pw, pb);
    k_wrearr<<<972, 256>>>(cw);
    k_q<<<(Bn * Nn) / 64, 256, smem_q>>>(x, qw, qb);
    k_nlwt<<<(Bn * N4 * Cc) / 256, 256>>>(x);
    k_conv<<<Bn, 256, smem_conv>>>(cb);
    k_kv<<<(Bn * N4) / 64, 256, smem_kv>>>(0, klw, klb, lsl);
    k_kv<<<(Bn * N4) / 64, 256, smem_kv>>>(1, khw, khb, lsh);
    k_attn<<<dim3(Bn * Hh, 2), 256, smem_attn>>>();
    k_fuse<<<Bn * 8, 256, smem_fuse>>>(out);
}